// round 1
// baseline (speedup 1.0000x reference)
#include <cuda_runtime.h>
#include <math.h>

// ---------------------------------------------------------------------------
// MultiHeadSelfAttention: x[4,2048,1024] fp32
//   Q = (x@Wq)*scale, K = x@Wk, V = x@Wv   (scale = 64^-0.5 folded into Q GEMM)
//   per (b,h): flash attention over seq=2048, Dh=64
//   out = ctx@Wo + bo
// Baseline: fp32 SIMT tiled GEMM + flash attention. Scratch in __device__ globals.
// ---------------------------------------------------------------------------

#define BATCH   4
#define SEQ     2048
#define DIM     1024
#define NHEADS  16
#define DH      64
#define M_TOT   (BATCH * SEQ)   // 8192

__device__ float g_q[M_TOT * DIM];
__device__ float g_k[M_TOT * DIM];
__device__ float g_v[M_TOT * DIM];
__device__ float g_ctx[M_TOT * DIM];

// ---------------------------------------------------------------------------
// SGEMM: C[M,N] = alpha * A[M,K] @ B[K,N] (+ bias[N])
// BM=BN=128, BK=16, 256 threads, 8x8 microtile with split (4+4) register reads.
// ---------------------------------------------------------------------------
__global__ __launch_bounds__(256)
void sgemm_kernel(const float* __restrict__ A, const float* __restrict__ B,
                  float* __restrict__ C, int M, int N, int K,
                  float alpha, const float* __restrict__ bias)
{
    const int BM = 128, BN = 128, BK = 16;
    __shared__ float As[16][129];   // [k][m], padded
    __shared__ float Bs[16][128];   // [k][n]

    const int tid = threadIdx.x;
    const int tx = tid & 15;        // 0..15  -> N microtile
    const int ty = tid >> 4;        // 0..15  -> M microtile
    const int row0 = blockIdx.y * BM;
    const int col0 = blockIdx.x * BN;

    float acc[8][8];
    #pragma unroll
    for (int i = 0; i < 8; i++)
        #pragma unroll
        for (int j = 0; j < 8; j++) acc[i][j] = 0.0f;

    for (int kt = 0; kt < K; kt += BK) {
        // Load A tile (128 x 16) as float4, store transposed into As[k][m]
        #pragma unroll
        for (int i = 0; i < 2; i++) {
            int idx = tid + i * 256;          // 0..511
            int ar  = idx >> 2;               // 0..127 (m)
            int ac  = (idx & 3) * 4;          // 0,4,8,12 (k)
            float4 va = *reinterpret_cast<const float4*>(
                &A[(size_t)(row0 + ar) * K + kt + ac]);
            As[ac + 0][ar] = va.x;
            As[ac + 1][ar] = va.y;
            As[ac + 2][ar] = va.z;
            As[ac + 3][ar] = va.w;
        }
        // Load B tile (16 x 128) as float4, row-major
        #pragma unroll
        for (int i = 0; i < 2; i++) {
            int idx = tid + i * 256;          // 0..511
            int br  = idx >> 5;               // 0..15 (k)
            int bc  = (idx & 31) * 4;         // 0..124 (n)
            *reinterpret_cast<float4*>(&Bs[br][bc]) =
                *reinterpret_cast<const float4*>(
                    &B[(size_t)(kt + br) * N + col0 + bc]);
        }
        __syncthreads();

        #pragma unroll
        for (int k = 0; k < BK; k++) {
            float ra[8], rb[8];
            #pragma unroll
            for (int i = 0; i < 4; i++) {
                ra[i]     = As[k][ty * 4 + i];
                ra[4 + i] = As[k][64 + ty * 4 + i];
            }
            #pragma unroll
            for (int j = 0; j < 4; j++) {
                rb[j]     = Bs[k][tx * 4 + j];
                rb[4 + j] = Bs[k][64 + tx * 4 + j];
            }
            #pragma unroll
            for (int i = 0; i < 8; i++)
                #pragma unroll
                for (int j = 0; j < 8; j++)
                    acc[i][j] += ra[i] * rb[j];
        }
        __syncthreads();
    }

    // Epilogue: split microtile rows {ty*4, 64+ty*4}, cols {tx*4, 64+tx*4}
    #pragma unroll
    for (int ih = 0; ih < 2; ih++) {
        #pragma unroll
        for (int i = 0; i < 4; i++) {
            int r = row0 + ih * 64 + ty * 4 + i;
            #pragma unroll
            for (int jh = 0; jh < 2; jh++) {
                int c = col0 + jh * 64 + tx * 4;
                float4 v;
                v.x = acc[ih * 4 + i][jh * 4 + 0] * alpha;
                v.y = acc[ih * 4 + i][jh * 4 + 1] * alpha;
                v.z = acc[ih * 4 + i][jh * 4 + 2] * alpha;
                v.w = acc[ih * 4 + i][jh * 4 + 3] * alpha;
                if (bias) {
                    v.x += bias[c + 0];
                    v.y += bias[c + 1];
                    v.z += bias[c + 2];
                    v.w += bias[c + 3];
                }
                *reinterpret_cast<float4*>(&C[(size_t)r * N + c]) = v;
            }
        }
    }
}

// ---------------------------------------------------------------------------
// Flash attention, fp32. Grid: (SEQ/BQ, BATCH*NHEADS). 256 threads.
// Layouts: Q/K/V/ctx all [M_TOT, DIM]; head h occupies cols [h*64, h*64+64).
// Thread map: ty=tid/16 owns 4 query rows; tx=tid%16 owns 2 score cols / 4 O dims.
// ---------------------------------------------------------------------------
#define BQ  64
#define BKV 32

__global__ __launch_bounds__(256)
void flash_attn_kernel(const float* __restrict__ Q, const float* __restrict__ K,
                       const float* __restrict__ V, float* __restrict__ O)
{
    __shared__ float Qs[BQ][DH + 1];    // 64x65
    __shared__ float Ks[BKV][DH + 1];   // 32x65
    __shared__ float Vs[BKV][DH + 1];   // 32x65
    __shared__ float Ps[BQ][BKV + 1];   // 64x33

    const int tid = threadIdx.x;
    const int tx = tid & 15;
    const int ty = tid >> 4;
    const int q0 = blockIdx.x * BQ;
    const int bh = blockIdx.y;
    const int b  = bh >> 4;
    const int h  = bh & 15;
    const size_t base = (size_t)b * SEQ * DIM + (size_t)h * DH;  // + s*DIM + d

    // Load Q tile (64 x 64): 1024 float4 / 256 threads = 4 each
    #pragma unroll
    for (int i = 0; i < 4; i++) {
        int idx = tid + i * 256;
        int r   = idx >> 4;          // 0..63
        int c4  = (idx & 15) * 4;    // 0..60
        float4 v = *reinterpret_cast<const float4*>(
            &Q[base + (size_t)(q0 + r) * DIM + c4]);
        Qs[r][c4 + 0] = v.x; Qs[r][c4 + 1] = v.y;
        Qs[r][c4 + 2] = v.z; Qs[r][c4 + 3] = v.w;
    }

    float m_i[4], l_i[4], acc[4][4];
    #pragma unroll
    for (int i = 0; i < 4; i++) {
        m_i[i] = -1e30f;
        l_i[i] = 0.0f;
        #pragma unroll
        for (int j = 0; j < 4; j++) acc[i][j] = 0.0f;
    }

    for (int kt = 0; kt < SEQ; kt += BKV) {
        // Load K,V tiles (32 x 64): 512 float4 each / 256 threads = 2 each
        #pragma unroll
        for (int i = 0; i < 2; i++) {
            int idx = tid + i * 256;
            int r   = idx >> 4;
            int c4  = (idx & 15) * 4;
            float4 kv = *reinterpret_cast<const float4*>(
                &K[base + (size_t)(kt + r) * DIM + c4]);
            Ks[r][c4 + 0] = kv.x; Ks[r][c4 + 1] = kv.y;
            Ks[r][c4 + 2] = kv.z; Ks[r][c4 + 3] = kv.w;
            float4 vv = *reinterpret_cast<const float4*>(
                &V[base + (size_t)(kt + r) * DIM + c4]);
            Vs[r][c4 + 0] = vv.x; Vs[r][c4 + 1] = vv.y;
            Vs[r][c4 + 2] = vv.z; Vs[r][c4 + 3] = vv.w;
        }
        __syncthreads();

        // Scores: s[i][j], rows ty*4+i, cols tx*2+j
        float s[4][2];
        #pragma unroll
        for (int i = 0; i < 4; i++) { s[i][0] = 0.0f; s[i][1] = 0.0f; }
        #pragma unroll
        for (int d = 0; d < DH; d++) {
            float rq[4], rk[2];
            #pragma unroll
            for (int i = 0; i < 4; i++) rq[i] = Qs[ty * 4 + i][d];
            rk[0] = Ks[tx * 2 + 0][d];
            rk[1] = Ks[tx * 2 + 1][d];
            #pragma unroll
            for (int i = 0; i < 4; i++) {
                s[i][0] += rq[i] * rk[0];
                s[i][1] += rq[i] * rk[1];
            }
        }

        // Online softmax (row reductions across the 16 tx lanes; lanes 0-15 and
        // 16-31 of a warp are distinct ty groups, xor masks <=8 stay in-group)
        float p[4][2], rsum[4], corr[4];
        #pragma unroll
        for (int i = 0; i < 4; i++) {
            float tmax = fmaxf(s[i][0], s[i][1]);
            #pragma unroll
            for (int off = 8; off >= 1; off >>= 1)
                tmax = fmaxf(tmax, __shfl_xor_sync(0xffffffffu, tmax, off));
            float mnew = fmaxf(m_i[i], tmax);
            corr[i] = __expf(m_i[i] - mnew);
            m_i[i]  = mnew;
            p[i][0] = __expf(s[i][0] - mnew);
            p[i][1] = __expf(s[i][1] - mnew);
            float rs = p[i][0] + p[i][1];
            #pragma unroll
            for (int off = 8; off >= 1; off >>= 1)
                rs += __shfl_xor_sync(0xffffffffu, rs, off);
            rsum[i] = rs;
        }
        #pragma unroll
        for (int i = 0; i < 4; i++) {
            l_i[i] = l_i[i] * corr[i] + rsum[i];
            #pragma unroll
            for (int j = 0; j < 4; j++) acc[i][j] *= corr[i];
            Ps[ty * 4 + i][tx * 2 + 0] = p[i][0];
            Ps[ty * 4 + i][tx * 2 + 1] = p[i][1];
        }
        __syncthreads();

        // PV: acc[i][dj] += sum_j Ps[row][j] * Vs[j][tx*4+dj]
        #pragma unroll
        for (int j = 0; j < BKV; j++) {
            float rv[4];
            #pragma unroll
            for (int dj = 0; dj < 4; dj++) rv[dj] = Vs[j][tx * 4 + dj];
            #pragma unroll
            for (int i = 0; i < 4; i++) {
                float pp = Ps[ty * 4 + i][j];
                #pragma unroll
                for (int dj = 0; dj < 4; dj++) acc[i][dj] += pp * rv[dj];
            }
        }
        __syncthreads();
    }

    // Epilogue: normalize and store to ctx [M_TOT, DIM]
    #pragma unroll
    for (int i = 0; i < 4; i++) {
        float inv = 1.0f / l_i[i];
        float4 v;
        v.x = acc[i][0] * inv;
        v.y = acc[i][1] * inv;
        v.z = acc[i][2] * inv;
        v.w = acc[i][3] * inv;
        *reinterpret_cast<float4*>(
            &O[base + (size_t)(q0 + ty * 4 + i) * DIM + tx * 4]) = v;
    }
}

// ---------------------------------------------------------------------------
// Launch
// ---------------------------------------------------------------------------
extern "C" void kernel_launch(void* const* d_in, const int* in_sizes, int n_in,
                              void* d_out, int out_size)
{
    const float* x  = (const float*)d_in[0];
    const float* Wq = (const float*)d_in[1];
    const float* Wk = (const float*)d_in[2];
    const float* Wv = (const float*)d_in[3];
    const float* Wo = (const float*)d_in[4];
    const float* bo = (const float*)d_in[5];
    float* out = (float*)d_out;

    float* q;   cudaGetSymbolAddress((void**)&q,   g_q);
    float* k;   cudaGetSymbolAddress((void**)&k,   g_k);
    float* v;   cudaGetSymbolAddress((void**)&v,   g_v);
    float* ctx; cudaGetSymbolAddress((void**)&ctx, g_ctx);

    const float scale = 0.125f;  // 64^-0.5

    dim3 gemm_grid(DIM / 128, M_TOT / 128);  // (8, 64)
    sgemm_kernel<<<gemm_grid, 256>>>(x, Wq, q, M_TOT, DIM, DIM, scale, nullptr);
    sgemm_kernel<<<gemm_grid, 256>>>(x, Wk, k, M_TOT, DIM, DIM, 1.0f, nullptr);
    sgemm_kernel<<<gemm_grid, 256>>>(x, Wv, v, M_TOT, DIM, DIM, 1.0f, nullptr);

    dim3 attn_grid(SEQ / BQ, BATCH * NHEADS);  // (32, 64)
    flash_attn_kernel<<<attn_grid, 256>>>(q, k, v, ctx);

    sgemm_kernel<<<gemm_grid, 256>>>(ctx, Wo, out, M_TOT, DIM, DIM, 1.0f, bo);
}

// round 3
// speedup vs baseline: 3.5578x; 3.5578x over previous
#include <cuda_runtime.h>
#include <math.h>
#include <stdint.h>

// ---------------------------------------------------------------------------
// MultiHeadSelfAttention via mma.sync tf32 tensor cores everywhere.
//   Q = (x@Wq)*scale, K = x@Wk, V = x@Wv
//   flash attention per (b,h), seq=2048, Dh=64
//   out = ctx@Wo + bo
// ---------------------------------------------------------------------------

#define BATCH   4
#define SEQ     2048
#define DIM     1024
#define NHEADS  16
#define DH      64
#define M_TOT   (BATCH * SEQ)   // 8192

__device__ float g_q[M_TOT * DIM];
__device__ float g_k[M_TOT * DIM];
__device__ float g_v[M_TOT * DIM];
__device__ float g_ctx[M_TOT * DIM];

// ---- tf32 helpers ---------------------------------------------------------
__device__ __forceinline__ uint32_t f2tf(float f) {
    uint32_t r;
    asm("cvt.rna.tf32.f32 %0, %1;" : "=r"(r) : "f"(f));
    return r;
}
__device__ __forceinline__ void mma8(float* c, const uint32_t* a, const uint32_t* b) {
    asm volatile(
        "mma.sync.aligned.m16n8k8.row.col.f32.tf32.tf32.f32 "
        "{%0,%1,%2,%3},{%4,%5,%6,%7},{%8,%9},{%0,%1,%2,%3};"
        : "+f"(c[0]), "+f"(c[1]), "+f"(c[2]), "+f"(c[3])
        : "r"(a[0]), "r"(a[1]), "r"(a[2]), "r"(a[3]), "r"(b[0]), "r"(b[1]));
}
__device__ __forceinline__ void ldsm4(uint32_t* r, const uint32_t* gptr) {
    uint32_t addr = (uint32_t)__cvta_generic_to_shared(gptr);
    asm volatile(
        "ldmatrix.sync.aligned.m8n8.x4.shared.b16 {%0,%1,%2,%3}, [%4];"
        : "=r"(r[0]), "=r"(r[1]), "=r"(r[2]), "=r"(r[3]) : "r"(addr));
}

// ---------------------------------------------------------------------------
// GEMM tf32: C[M,N] = alpha * A[M,K] @ B[K,N] (+ bias). M from grid.
// 256 thr = 8 warps (4 m x 2 n). BM=128 BN=128 BK=32. Warp tile 32x64.
// ---------------------------------------------------------------------------
#define GBM 128
#define GBN 128
#define GBK 32

__global__ __launch_bounds__(256)
void gemm_tf32(const float* __restrict__ A, const float* __restrict__ B,
               float* __restrict__ C, int K, int N_,
               float alpha, const float* __restrict__ bias)
{
    __shared__ uint32_t As[GBM][GBK + 4];   // 128 x 36
    __shared__ uint32_t Bs[GBK][GBN + 4];   // 32 x 132

    const int tid  = threadIdx.x;
    const int lane = tid & 31;
    const int wid  = tid >> 5;
    const int wm   = wid >> 1;          // 0..3
    const int wn   = wid & 1;           // 0..1
    const int gid  = lane >> 2;         // 0..7
    const int t4   = lane & 3;          // 0..3
    const int row0 = blockIdx.y * GBM;
    const int col0 = blockIdx.x * GBN;

    const int lt     = lane >> 3;
    const int a_row  = (lane & 7) + (lt & 1) * 8;
    const int a_colb = (lt >> 1) * 4;

    float acc[2][8][4];
    #pragma unroll
    for (int mi = 0; mi < 2; mi++)
        #pragma unroll
        for (int j = 0; j < 8; j++)
            #pragma unroll
            for (int q = 0; q < 4; q++) acc[mi][j][q] = 0.0f;

    for (int kt = 0; kt < K; kt += GBK) {
        // A tile 128x32
        #pragma unroll
        for (int p = 0; p < 4; p++) {
            int r  = (tid >> 3) + p * 32;
            int c4 = (tid & 7) * 4;
            float4 v = *(const float4*)&A[(size_t)(row0 + r) * K + kt + c4];
            *(uint4*)&As[r][c4] =
                make_uint4(f2tf(v.x), f2tf(v.y), f2tf(v.z), f2tf(v.w));
        }
        // B tile 32x128 (natural)
        #pragma unroll
        for (int p = 0; p < 4; p++) {
            int k  = (tid >> 5) + p * 8;
            int n4 = (tid & 31) * 4;
            float4 v = *(const float4*)&B[(size_t)(kt + k) * N_ + col0 + n4];
            *(uint4*)&Bs[k][n4] =
                make_uint4(f2tf(v.x), f2tf(v.y), f2tf(v.z), f2tf(v.w));
        }
        __syncthreads();

        #pragma unroll
        for (int s = 0; s < 4; s++) {
            uint32_t af[2][4];
            #pragma unroll
            for (int mi = 0; mi < 2; mi++)
                ldsm4(af[mi], &As[wm * 32 + mi * 16 + a_row][s * 8 + a_colb]);

            uint32_t bf[8][2];
            #pragma unroll
            for (int j = 0; j < 8; j++) {
                bf[j][0] = Bs[s * 8 + t4][wn * 64 + j * 8 + gid];
                bf[j][1] = Bs[s * 8 + 4 + t4][wn * 64 + j * 8 + gid];
            }
            #pragma unroll
            for (int mi = 0; mi < 2; mi++)
                #pragma unroll
                for (int j = 0; j < 8; j++)
                    mma8(acc[mi][j], af[mi], bf[j]);
        }
        __syncthreads();
    }

    // Epilogue
    #pragma unroll
    for (int mi = 0; mi < 2; mi++) {
        int r0 = row0 + wm * 32 + mi * 16 + gid;
        #pragma unroll
        for (int j = 0; j < 8; j++) {
            int c = col0 + wn * 64 + j * 8 + 2 * t4;
            float b0 = 0.0f, b1 = 0.0f;
            if (bias) { b0 = bias[c]; b1 = bias[c + 1]; }
            float2 v0 = { acc[mi][j][0] * alpha + b0, acc[mi][j][1] * alpha + b1 };
            float2 v1 = { acc[mi][j][2] * alpha + b0, acc[mi][j][3] * alpha + b1 };
            *(float2*)&C[(size_t)r0 * N_ + c]       = v0;
            *(float2*)&C[(size_t)(r0 + 8) * N_ + c] = v1;
        }
    }
}

// ---------------------------------------------------------------------------
// Flash attention, tf32 tensor cores. 128 thr = 4 warps x 16 q-rows.
// BQ=64, BKV=64. Q fragments register-resident. Dynamic smem (52224 B):
//   Ks [64][68], Vt [64][68], Ps [64][68]  (strides 272B = 16 mod 128,
//   conflict-free ldmatrix row addressing).
// ---------------------------------------------------------------------------
#define AQ  64
#define AKV 64
#define AST (DH + 4)   // 68
#define ATTN_SMEM_BYTES (3 * AQ * AST * 4)   // 52224

extern __shared__ uint32_t attn_smem[];

__global__ __launch_bounds__(128)
void attn_tf32(const float* __restrict__ Qg, const float* __restrict__ Kg,
               const float* __restrict__ Vg, float* __restrict__ O)
{
    uint32_t (*Ks)[AST] = (uint32_t (*)[AST])(attn_smem);                 // [kv][d]
    uint32_t (*Vt)[AST] = (uint32_t (*)[AST])(attn_smem + AQ * AST);      // [d][kv]
    uint32_t (*Ps)[AST] = (uint32_t (*)[AST])(attn_smem + 2 * AQ * AST);  // P / Q stage

    const int tid  = threadIdx.x;
    const int lane = tid & 31;
    const int w    = tid >> 5;
    const int gid  = lane >> 2;
    const int t4   = lane & 3;
    const int q0   = blockIdx.x * AQ;
    const int bh   = blockIdx.y;
    const size_t base = (size_t)(bh >> 4) * SEQ * DIM + (size_t)(bh & 15) * DH;

    const int lt     = lane >> 3;
    const int a_row  = (lane & 7) + (lt & 1) * 8;   // A-frag (a0,a1,a2,a3)
    const int a_colb = (lt >> 1) * 4;
    const int b_rowb = (lt >> 1) * 8;               // B-frag pair layout
    const int b_row  = (lane & 7);
    const int b_colb = (lt & 1) * 4;

    // Stage Q into Ps, pull A-fragments to regs
    #pragma unroll
    for (int p = 0; p < 8; p++) {
        int r  = (tid >> 4) + p * 8;
        int c4 = (tid & 15) * 4;
        float4 v = *(const float4*)&Qg[base + (size_t)(q0 + r) * DIM + c4];
        *(uint4*)&Ps[r][c4] = make_uint4(f2tf(v.x), f2tf(v.y), f2tf(v.z), f2tf(v.w));
    }
    __syncthreads();
    uint32_t qa[8][4];
    #pragma unroll
    for (int s = 0; s < 8; s++)
        ldsm4(qa[s], &Ps[w * 16 + a_row][s * 8 + a_colb]);
    __syncthreads();

    float m0 = -1e30f, m1 = -1e30f, l0 = 0.0f, l1 = 0.0f;
    float oc[8][4];
    #pragma unroll
    for (int j = 0; j < 8; j++)
        #pragma unroll
        for (int q = 0; q < 4; q++) oc[j][q] = 0.0f;

    for (int kt = 0; kt < SEQ; kt += AKV) {
        // K tile [64][64], natural layout
        #pragma unroll
        for (int p = 0; p < 8; p++) {
            int r  = (tid >> 4) + p * 8;
            int c4 = (tid & 15) * 4;
            float4 v = *(const float4*)&Kg[base + (size_t)(kt + r) * DIM + c4];
            *(uint4*)&Ks[r][c4] = make_uint4(f2tf(v.x), f2tf(v.y), f2tf(v.z), f2tf(v.w));
        }
        // V tile transposed: coalesced LDG along d, STS.128 along kv
        {
            int d   = tid & 63;
            int kvh = tid >> 6;
            #pragma unroll
            for (int p = 0; p < 8; p++) {
                int kv0 = kvh * 4 + p * 8;
                uint4 u;
                u.x = f2tf(Vg[base + (size_t)(kt + kv0 + 0) * DIM + d]);
                u.y = f2tf(Vg[base + (size_t)(kt + kv0 + 1) * DIM + d]);
                u.z = f2tf(Vg[base + (size_t)(kt + kv0 + 2) * DIM + d]);
                u.w = f2tf(Vg[base + (size_t)(kt + kv0 + 3) * DIM + d]);
                *(uint4*)&Vt[d][kv0] = u;
            }
        }
        __syncthreads();

        // ---- S = Q @ K^T  (warp: 16 x 64) ----
        float sc[8][4];
        #pragma unroll
        for (int j = 0; j < 8; j++)
            #pragma unroll
            for (int q = 0; q < 4; q++) sc[j][q] = 0.0f;

        #pragma unroll
        for (int s = 0; s < 8; s++) {
            uint32_t kb[8][2];
            #pragma unroll
            for (int jp = 0; jp < 4; jp++) {
                uint32_t r4[4];
                ldsm4(r4, &Ks[jp * 16 + b_rowb + b_row][s * 8 + b_colb]);
                kb[jp * 2][0]     = r4[0];
                kb[jp * 2][1]     = r4[1];
                kb[jp * 2 + 1][0] = r4[2];
                kb[jp * 2 + 1][1] = r4[3];
            }
            #pragma unroll
            for (int j = 0; j < 8; j++)
                mma8(sc[j], qa[s], kb[j]);
        }

        // ---- online softmax ----
        float mx0 = -1e30f, mx1 = -1e30f;
        #pragma unroll
        for (int j = 0; j < 8; j++) {
            mx0 = fmaxf(mx0, fmaxf(sc[j][0], sc[j][1]));
            mx1 = fmaxf(mx1, fmaxf(sc[j][2], sc[j][3]));
        }
        mx0 = fmaxf(mx0, __shfl_xor_sync(0xffffffffu, mx0, 1));
        mx0 = fmaxf(mx0, __shfl_xor_sync(0xffffffffu, mx0, 2));
        mx1 = fmaxf(mx1, __shfl_xor_sync(0xffffffffu, mx1, 1));
        mx1 = fmaxf(mx1, __shfl_xor_sync(0xffffffffu, mx1, 2));
        float mn0 = fmaxf(m0, mx0), mn1 = fmaxf(m1, mx1);
        float cr0 = __expf(m0 - mn0), cr1 = __expf(m1 - mn1);
        m0 = mn0; m1 = mn1;

        float s0 = 0.0f, s1 = 0.0f;
        #pragma unroll
        for (int j = 0; j < 8; j++) {
            float p0 = __expf(sc[j][0] - mn0);
            float p1 = __expf(sc[j][1] - mn0);
            float p2 = __expf(sc[j][2] - mn1);
            float p3 = __expf(sc[j][3] - mn1);
            s0 += p0 + p1; s1 += p2 + p3;
            uint2 u0 = { f2tf(p0), f2tf(p1) };
            uint2 u1 = { f2tf(p2), f2tf(p3) };
            *(uint2*)&Ps[w * 16 + gid][j * 8 + 2 * t4]     = u0;
            *(uint2*)&Ps[w * 16 + gid + 8][j * 8 + 2 * t4] = u1;
        }
        s0 += __shfl_xor_sync(0xffffffffu, s0, 1);
        s0 += __shfl_xor_sync(0xffffffffu, s0, 2);
        s1 += __shfl_xor_sync(0xffffffffu, s1, 1);
        s1 += __shfl_xor_sync(0xffffffffu, s1, 2);
        l0 = l0 * cr0 + s0;
        l1 = l1 * cr1 + s1;
        #pragma unroll
        for (int j = 0; j < 8; j++) {
            oc[j][0] *= cr0; oc[j][1] *= cr0;
            oc[j][2] *= cr1; oc[j][3] *= cr1;
        }
        __syncwarp();

        // ---- O += P @ V ----
        #pragma unroll
        for (int s = 0; s < 8; s++) {
            uint32_t pa[4];
            ldsm4(pa, &Ps[w * 16 + a_row][s * 8 + a_colb]);
            #pragma unroll
            for (int jp = 0; jp < 4; jp++) {
                uint32_t r4[4];
                ldsm4(r4, &Vt[jp * 16 + b_rowb + b_row][s * 8 + b_colb]);
                mma8(oc[jp * 2],     pa, &r4[0]);
                mma8(oc[jp * 2 + 1], pa, &r4[2]);
            }
        }
        __syncthreads();
    }

    // Epilogue
    float inv0 = 1.0f / l0, inv1 = 1.0f / l1;
    int r0 = q0 + w * 16 + gid;
    #pragma unroll
    for (int j = 0; j < 8; j++) {
        int c = j * 8 + 2 * t4;
        float2 v0 = { oc[j][0] * inv0, oc[j][1] * inv0 };
        float2 v1 = { oc[j][2] * inv1, oc[j][3] * inv1 };
        *(float2*)&O[base + (size_t)r0 * DIM + c]       = v0;
        *(float2*)&O[base + (size_t)(r0 + 8) * DIM + c] = v1;
    }
}

// ---------------------------------------------------------------------------
// Launch
// ---------------------------------------------------------------------------
extern "C" void kernel_launch(void* const* d_in, const int* in_sizes, int n_in,
                              void* d_out, int out_size)
{
    const float* x  = (const float*)d_in[0];
    const float* Wq = (const float*)d_in[1];
    const float* Wk = (const float*)d_in[2];
    const float* Wv = (const float*)d_in[3];
    const float* Wo = (const float*)d_in[4];
    const float* bo = (const float*)d_in[5];
    float* out = (float*)d_out;

    float* q;   cudaGetSymbolAddress((void**)&q,   g_q);
    float* k;   cudaGetSymbolAddress((void**)&k,   g_k);
    float* v;   cudaGetSymbolAddress((void**)&v,   g_v);
    float* ctx; cudaGetSymbolAddress((void**)&ctx, g_ctx);

    cudaFuncSetAttribute(attn_tf32,
                         cudaFuncAttributeMaxDynamicSharedMemorySize,
                         ATTN_SMEM_BYTES);

    const float scale = 0.125f;  // 64^-0.5

    dim3 gemm_grid(DIM / GBN, M_TOT / GBM);  // (8, 64)
    gemm_tf32<<<gemm_grid, 256>>>(x, Wq, q, DIM, DIM, scale, nullptr);
    gemm_tf32<<<gemm_grid, 256>>>(x, Wk, k, DIM, DIM, 1.0f, nullptr);
    gemm_tf32<<<gemm_grid, 256>>>(x, Wv, v, DIM, DIM, 1.0f, nullptr);

    dim3 attn_grid(SEQ / AQ, BATCH * NHEADS);  // (32, 64)
    attn_tf32<<<attn_grid, 128, ATTN_SMEM_BYTES>>>(q, k, v, ctx);

    gemm_tf32<<<gemm_grid, 256>>>(ctx, Wo, out, DIM, DIM, 1.0f, bo);
}

// round 4
// speedup vs baseline: 3.8995x; 1.0961x over previous
#include <cuda_runtime.h>
#include <stdint.h>

// ---------------------------------------------------------------------------
// MultiHeadSelfAttention, tf32 mma.sync everywhere.
// R4: pre-truncated inputs (tf32-representable f32) -> conversion-free GEMM
//     with cp.async double buffering; QKV fused; attn uses ex2 + raw loads.
// ---------------------------------------------------------------------------

#define BATCH   4
#define SEQ     2048
#define DIM     1024
#define NHEADS  16
#define DH      64
#define M_TOT   (BATCH * SEQ)   // 8192

__device__ float g_xt[M_TOT * DIM];
__device__ float g_wq[DIM * DIM];
__device__ float g_wk[DIM * DIM];
__device__ float g_wv[DIM * DIM];
__device__ float g_wo[DIM * DIM];
__device__ float g_q[M_TOT * DIM];
__device__ float g_k[M_TOT * DIM];
__device__ float g_v[M_TOT * DIM];
__device__ float g_ctx[M_TOT * DIM];

// ---- helpers --------------------------------------------------------------
__device__ __forceinline__ uint32_t f2tf(float f) {
    uint32_t r;
    asm("cvt.rna.tf32.f32 %0, %1;" : "=r"(r) : "f"(f));
    return r;
}
__device__ __forceinline__ float ex2(float x) {
    float r;
    asm("ex2.approx.ftz.f32 %0, %1;" : "=f"(r) : "f"(x));
    return r;
}
__device__ __forceinline__ void mma8(float* c, const uint32_t* a, const uint32_t* b) {
    asm volatile(
        "mma.sync.aligned.m16n8k8.row.col.f32.tf32.tf32.f32 "
        "{%0,%1,%2,%3},{%4,%5,%6,%7},{%8,%9},{%0,%1,%2,%3};"
        : "+f"(c[0]), "+f"(c[1]), "+f"(c[2]), "+f"(c[3])
        : "r"(a[0]), "r"(a[1]), "r"(a[2]), "r"(a[3]), "r"(b[0]), "r"(b[1]));
}
__device__ __forceinline__ void ldsm4(uint32_t* r, const uint32_t* gptr) {
    uint32_t addr = (uint32_t)__cvta_generic_to_shared(gptr);
    asm volatile(
        "ldmatrix.sync.aligned.m8n8.x4.shared.b16 {%0,%1,%2,%3}, [%4];"
        : "=r"(r[0]), "=r"(r[1]), "=r"(r[2]), "=r"(r[3]) : "r"(addr));
}
__device__ __forceinline__ void cpasync16(void* dst, const void* src) {
    uint32_t d = (uint32_t)__cvta_generic_to_shared(dst);
    asm volatile("cp.async.cg.shared.global [%0], [%1], 16;" :: "r"(d), "l"(src));
}

extern __shared__ uint32_t dyn_smem[];

// ---------------------------------------------------------------------------
// Pre-truncation: dst = round_to_tf32(src), as f32 bits.
// ---------------------------------------------------------------------------
__global__ void trunc_kernel(const float* __restrict__ src, float* __restrict__ dst,
                             int n4)
{
    int i = blockIdx.x * blockDim.x + threadIdx.x;
    if (i < n4) {
        float4 v = ((const float4*)src)[i];
        uint4 u = make_uint4(f2tf(v.x), f2tf(v.y), f2tf(v.z), f2tf(v.w));
        ((uint4*)dst)[i] = u;
    }
}

// ---------------------------------------------------------------------------
// GEMM body: C[row0:+128, col0:+128] = alpha * A @ B (+bias), K = DIM.
// cp.async 2-stage pipeline. Inputs must be tf32-representable f32.
// 256 thr = 8 warps (4m x 2n), warp tile 32x64, BK=32.
// ---------------------------------------------------------------------------
#define GBK   32
#define KT    (DIM / GBK)     // 32
#define A_ST  36
#define B_ST  132
#define A_TILE (128 * A_ST)   // 4608 u32
#define B_TILE (GBK * B_ST)   // 4224 u32
#define GEMM_SMEM ((2 * A_TILE + 2 * B_TILE) * 4)   // 70656 B

__device__ __forceinline__ void gemm_body(
    const float* __restrict__ A, const float* __restrict__ B, float* __restrict__ C,
    int row0, int col0, float alpha, const float* __restrict__ bias, bool trunc)
{
    uint32_t* As = dyn_smem;                 // [2][128][36]
    uint32_t* Bs = dyn_smem + 2 * A_TILE;    // [2][32][132]

    const int tid  = threadIdx.x;
    const int lane = tid & 31;
    const int wid  = tid >> 5;
    const int wm   = wid >> 1;
    const int wn   = wid & 1;
    const int gid  = lane >> 2;
    const int t4   = lane & 3;
    const int lt     = lane >> 3;
    const int a_row  = (lane & 7) + (lt & 1) * 8;
    const int a_colb = (lt >> 1) * 4;

    // per-thread load coords
    const int ar = tid >> 3, ac4 = (tid & 7) * 4;
    const int bk = tid >> 5, bn4 = (tid & 31) * 4;

    float acc[2][8][4];
    #pragma unroll
    for (int mi = 0; mi < 2; mi++)
        #pragma unroll
        for (int j = 0; j < 8; j++)
            #pragma unroll
            for (int q = 0; q < 4; q++) acc[mi][j][q] = 0.0f;

    // issue tile kt_i into buffer buf
    auto issue = [&](int kt_i, int buf) {
        int kt = kt_i * GBK;
        #pragma unroll
        for (int p = 0; p < 4; p++) {
            int r = ar + p * 32;
            cpasync16(&As[buf * A_TILE + r * A_ST + ac4],
                      &A[(size_t)(row0 + r) * DIM + kt + ac4]);
        }
        #pragma unroll
        for (int p = 0; p < 4; p++) {
            int k = bk + p * 8;
            cpasync16(&Bs[buf * B_TILE + k * B_ST + bn4],
                      &B[(size_t)(kt + k) * DIM + col0 + bn4]);
        }
        asm volatile("cp.async.commit_group;" ::);
    };

    issue(0, 0);
    for (int kt_i = 0; kt_i < KT; kt_i++) {
        if (kt_i + 1 < KT) {
            issue(kt_i + 1, (kt_i + 1) & 1);
            asm volatile("cp.async.wait_group 1;" ::);
        } else {
            asm volatile("cp.async.wait_group 0;" ::);
        }
        __syncthreads();

        const uint32_t* Asb = &As[(kt_i & 1) * A_TILE];
        const uint32_t* Bsb = &Bs[(kt_i & 1) * B_TILE];
        #pragma unroll
        for (int s = 0; s < 4; s++) {
            uint32_t af[2][4];
            #pragma unroll
            for (int mi = 0; mi < 2; mi++)
                ldsm4(af[mi], &Asb[(wm * 32 + mi * 16 + a_row) * A_ST + s * 8 + a_colb]);

            uint32_t bf[8][2];
            #pragma unroll
            for (int j = 0; j < 8; j++) {
                bf[j][0] = Bsb[(s * 8 + t4) * B_ST + wn * 64 + j * 8 + gid];
                bf[j][1] = Bsb[(s * 8 + 4 + t4) * B_ST + wn * 64 + j * 8 + gid];
            }
            #pragma unroll
            for (int mi = 0; mi < 2; mi++)
                #pragma unroll
                for (int j = 0; j < 8; j++)
                    mma8(acc[mi][j], af[mi], bf[j]);
        }
        __syncthreads();
    }

    // Epilogue
    #pragma unroll
    for (int mi = 0; mi < 2; mi++) {
        int r0 = row0 + wm * 32 + mi * 16 + gid;
        #pragma unroll
        for (int j = 0; j < 8; j++) {
            int c = col0 + wn * 64 + j * 8 + 2 * t4;
            float b0 = 0.0f, b1 = 0.0f;
            if (bias) { b0 = bias[c]; b1 = bias[c + 1]; }
            float o00 = acc[mi][j][0] * alpha + b0;
            float o01 = acc[mi][j][1] * alpha + b1;
            float o10 = acc[mi][j][2] * alpha + b0;
            float o11 = acc[mi][j][3] * alpha + b1;
            float2 v0, v1;
            if (trunc) {
                v0 = make_float2(__uint_as_float(f2tf(o00)), __uint_as_float(f2tf(o01)));
                v1 = make_float2(__uint_as_float(f2tf(o10)), __uint_as_float(f2tf(o11)));
            } else {
                v0 = make_float2(o00, o01);
                v1 = make_float2(o10, o11);
            }
            *(float2*)&C[(size_t)r0 * DIM + c]       = v0;
            *(float2*)&C[(size_t)(r0 + 8) * DIM + c] = v1;
        }
    }
}

// alpha for Q: attn scale * log2(e) folded in (softmax uses ex2)
#define Q_ALPHA 0.18033688011112042f   // 0.125 * log2(e)

__global__ __launch_bounds__(256, 2)
void qkv_gemm()
{
    int widx = blockIdx.x >> 3;
    int col0 = (blockIdx.x & 7) * 128;
    int row0 = blockIdx.y * 128;
    const float* W = (widx == 0) ? g_wq : (widx == 1) ? g_wk : g_wv;
    float*       C = (widx == 0) ? g_q  : (widx == 1) ? g_k  : g_v;
    float alpha    = (widx == 0) ? Q_ALPHA : 1.0f;
    gemm_body(g_xt, W, C, row0, col0, alpha, nullptr, true);
}

__global__ __launch_bounds__(256, 2)
void out_gemm(float* __restrict__ outp, const float* __restrict__ bias)
{
    gemm_body(g_ctx, g_wo, outp, blockIdx.y * 128, blockIdx.x * 128, 1.0f, bias, false);
}

// ---------------------------------------------------------------------------
// Flash attention, tf32. 128 thr = 4 warps x 16 q-rows. BQ=64, BKV=64.
// Inputs pre-truncated (raw bit loads). Softmax in log2 domain (ex2).
// ---------------------------------------------------------------------------
#define AQ  64
#define AKV 64
#define AST (DH + 4)   // 68
#define ATTN_SMEM_BYTES (3 * AQ * AST * 4)   // 52224

__global__ __launch_bounds__(128, 4)
void attn_tf32(float* __restrict__ O)
{
    const float* Qg = g_q;
    const float* Kg = g_k;
    const float* Vg = g_v;

    uint32_t (*Ks)[AST] = (uint32_t (*)[AST])(dyn_smem);                 // [kv][d]
    uint32_t (*Vt)[AST] = (uint32_t (*)[AST])(dyn_smem + AQ * AST);      // [d][kv]
    uint32_t (*Ps)[AST] = (uint32_t (*)[AST])(dyn_smem + 2 * AQ * AST);  // P / Q stage

    const int tid  = threadIdx.x;
    const int lane = tid & 31;
    const int w    = tid >> 5;
    const int gid  = lane >> 2;
    const int t4   = lane & 3;
    const int q0   = blockIdx.x * AQ;
    const int bh   = blockIdx.y;
    const size_t base = (size_t)(bh >> 4) * SEQ * DIM + (size_t)(bh & 15) * DH;

    const int lt     = lane >> 3;
    const int a_row  = (lane & 7) + (lt & 1) * 8;
    const int a_colb = (lt >> 1) * 4;
    const int b_rowb = (lt >> 1) * 8;
    const int b_row  = (lane & 7);
    const int b_colb = (lt & 1) * 4;

    // Stage Q into Ps (raw bits), pull A-fragments to regs
    #pragma unroll
    for (int p = 0; p < 8; p++) {
        int r  = (tid >> 4) + p * 8;
        int c4 = (tid & 15) * 4;
        *(uint4*)&Ps[r][c4] =
            *(const uint4*)&Qg[base + (size_t)(q0 + r) * DIM + c4];
    }
    __syncthreads();
    uint32_t qa[8][4];
    #pragma unroll
    for (int s = 0; s < 8; s++)
        ldsm4(qa[s], &Ps[w * 16 + a_row][s * 8 + a_colb]);
    __syncthreads();

    float m0 = -1e30f, m1 = -1e30f, l0 = 0.0f, l1 = 0.0f;
    float oc[8][4];
    #pragma unroll
    for (int j = 0; j < 8; j++)
        #pragma unroll
        for (int q = 0; q < 4; q++) oc[j][q] = 0.0f;

    for (int kt = 0; kt < SEQ; kt += AKV) {
        // K tile [64][64] raw copy
        #pragma unroll
        for (int p = 0; p < 8; p++) {
            int r  = (tid >> 4) + p * 8;
            int c4 = (tid & 15) * 4;
            *(uint4*)&Ks[r][c4] =
                *(const uint4*)&Kg[base + (size_t)(kt + r) * DIM + c4];
        }
        // V tile transposed
        {
            int d   = tid & 63;
            int kvh = tid >> 6;
            #pragma unroll
            for (int p = 0; p < 8; p++) {
                int kv0 = kvh * 4 + p * 8;
                uint4 u;
                u.x = __float_as_uint(Vg[base + (size_t)(kt + kv0 + 0) * DIM + d]);
                u.y = __float_as_uint(Vg[base + (size_t)(kt + kv0 + 1) * DIM + d]);
                u.z = __float_as_uint(Vg[base + (size_t)(kt + kv0 + 2) * DIM + d]);
                u.w = __float_as_uint(Vg[base + (size_t)(kt + kv0 + 3) * DIM + d]);
                *(uint4*)&Vt[d][kv0] = u;
            }
        }
        __syncthreads();

        // ---- S = Q @ K^T ----
        float sc[8][4];
        #pragma unroll
        for (int j = 0; j < 8; j++)
            #pragma unroll
            for (int q = 0; q < 4; q++) sc[j][q] = 0.0f;

        #pragma unroll
        for (int s = 0; s < 8; s++) {
            uint32_t kb[8][2];
            #pragma unroll
            for (int jp = 0; jp < 4; jp++) {
                uint32_t r4[4];
                ldsm4(r4, &Ks[jp * 16 + b_rowb + b_row][s * 8 + b_colb]);
                kb[jp * 2][0]     = r4[0];
                kb[jp * 2][1]     = r4[1];
                kb[jp * 2 + 1][0] = r4[2];
                kb[jp * 2 + 1][1] = r4[3];
            }
            #pragma unroll
            for (int j = 0; j < 8; j++)
                mma8(sc[j], qa[s], kb[j]);
        }

        // ---- online softmax (log2 domain) ----
        float mx0 = -1e30f, mx1 = -1e30f;
        #pragma unroll
        for (int j = 0; j < 8; j++) {
            mx0 = fmaxf(mx0, fmaxf(sc[j][0], sc[j][1]));
            mx1 = fmaxf(mx1, fmaxf(sc[j][2], sc[j][3]));
        }
        mx0 = fmaxf(mx0, __shfl_xor_sync(0xffffffffu, mx0, 1));
        mx0 = fmaxf(mx0, __shfl_xor_sync(0xffffffffu, mx0, 2));
        mx1 = fmaxf(mx1, __shfl_xor_sync(0xffffffffu, mx1, 1));
        mx1 = fmaxf(mx1, __shfl_xor_sync(0xffffffffu, mx1, 2));
        float mn0 = fmaxf(m0, mx0), mn1 = fmaxf(m1, mx1);
        float cr0 = ex2(m0 - mn0), cr1 = ex2(m1 - mn1);
        m0 = mn0; m1 = mn1;

        float s0 = 0.0f, s1 = 0.0f;
        #pragma unroll
        for (int j = 0; j < 8; j++) {
            float p0 = ex2(sc[j][0] - mn0);
            float p1 = ex2(sc[j][1] - mn0);
            float p2 = ex2(sc[j][2] - mn1);
            float p3 = ex2(sc[j][3] - mn1);
            s0 += p0 + p1; s1 += p2 + p3;
            uint2 u0 = { f2tf(p0), f2tf(p1) };
            uint2 u1 = { f2tf(p2), f2tf(p3) };
            *(uint2*)&Ps[w * 16 + gid][j * 8 + 2 * t4]     = u0;
            *(uint2*)&Ps[w * 16 + gid + 8][j * 8 + 2 * t4] = u1;
        }
        s0 += __shfl_xor_sync(0xffffffffu, s0, 1);
        s0 += __shfl_xor_sync(0xffffffffu, s0, 2);
        s1 += __shfl_xor_sync(0xffffffffu, s1, 1);
        s1 += __shfl_xor_sync(0xffffffffu, s1, 2);
        l0 = l0 * cr0 + s0;
        l1 = l1 * cr1 + s1;
        #pragma unroll
        for (int j = 0; j < 8; j++) {
            oc[j][0] *= cr0; oc[j][1] *= cr0;
            oc[j][2] *= cr1; oc[j][3] *= cr1;
        }
        __syncwarp();

        // ---- O += P @ V ----
        #pragma unroll
        for (int s = 0; s < 8; s++) {
            uint32_t pa[4];
            ldsm4(pa, &Ps[w * 16 + a_row][s * 8 + a_colb]);
            #pragma unroll
            for (int jp = 0; jp < 4; jp++) {
                uint32_t r4[4];
                ldsm4(r4, &Vt[jp * 16 + b_rowb + b_row][s * 8 + b_colb]);
                mma8(oc[jp * 2],     pa, &r4[0]);
                mma8(oc[jp * 2 + 1], pa, &r4[2]);
            }
        }
        __syncthreads();
    }

    // Epilogue: normalize + truncate (ctx feeds another tf32 GEMM)
    float inv0 = 1.0f / l0, inv1 = 1.0f / l1;
    int r0 = q0 + w * 16 + gid;
    #pragma unroll
    for (int j = 0; j < 8; j++) {
        int c = j * 8 + 2 * t4;
        uint2 v0 = { f2tf(oc[j][0] * inv0), f2tf(oc[j][1] * inv0) };
        uint2 v1 = { f2tf(oc[j][2] * inv1), f2tf(oc[j][3] * inv1) };
        *(uint2*)&O[base + (size_t)r0 * DIM + c]       = *(uint2*)&v0;
        *(uint2*)&O[base + (size_t)(r0 + 8) * DIM + c] = *(uint2*)&v1;
    }
}

// ---------------------------------------------------------------------------
// Launch
// ---------------------------------------------------------------------------
extern "C" void kernel_launch(void* const* d_in, const int* in_sizes, int n_in,
                              void* d_out, int out_size)
{
    const float* x  = (const float*)d_in[0];
    const float* Wq = (const float*)d_in[1];
    const float* Wk = (const float*)d_in[2];
    const float* Wv = (const float*)d_in[3];
    const float* Wo = (const float*)d_in[4];
    const float* bo = (const float*)d_in[5];
    float* out = (float*)d_out;

    float *xt, *wq, *wk, *wv, *wo, *ctx;
    cudaGetSymbolAddress((void**)&xt,  g_xt);
    cudaGetSymbolAddress((void**)&wq,  g_wq);
    cudaGetSymbolAddress((void**)&wk,  g_wk);
    cudaGetSymbolAddress((void**)&wv,  g_wv);
    cudaGetSymbolAddress((void**)&wo,  g_wo);
    cudaGetSymbolAddress((void**)&ctx, g_ctx);

    cudaFuncSetAttribute(qkv_gemm, cudaFuncAttributeMaxDynamicSharedMemorySize, GEMM_SMEM);
    cudaFuncSetAttribute(out_gemm, cudaFuncAttributeMaxDynamicSharedMemorySize, GEMM_SMEM);
    cudaFuncSetAttribute(attn_tf32, cudaFuncAttributeMaxDynamicSharedMemorySize, ATTN_SMEM_BYTES);

    // Pre-truncate inputs to tf32-representable f32
    {
        int n4x = (M_TOT * DIM) / 4;
        trunc_kernel<<<(n4x + 255) / 256, 256>>>(x, xt, n4x);
        int n4w = (DIM * DIM) / 4;
        trunc_kernel<<<(n4w + 255) / 256, 256>>>(Wq, wq, n4w);
        trunc_kernel<<<(n4w + 255) / 256, 256>>>(Wk, wk, n4w);
        trunc_kernel<<<(n4w + 255) / 256, 256>>>(Wv, wv, n4w);
        trunc_kernel<<<(n4w + 255) / 256, 256>>>(Wo, wo, n4w);
    }

    qkv_gemm<<<dim3(24, M_TOT / 128), 256, GEMM_SMEM>>>();
    attn_tf32<<<dim3(SEQ / AQ, BATCH * NHEADS), 128, ATTN_SMEM_BYTES>>>(ctx);
    out_gemm<<<dim3(DIM / 128, M_TOT / 128), 256, GEMM_SMEM>>>(out, bo);
}

// round 5
// speedup vs baseline: 3.9208x; 1.0055x over previous
#include <cuda_runtime.h>
#include <stdint.h>

// ---------------------------------------------------------------------------
// MultiHeadSelfAttention, tf32 mma.sync.
// R5: V stored transposed at projection; attention uses cp.async double
//     buffering for K/V^T; P kept in registers via quad shuffles.
// ---------------------------------------------------------------------------

#define BATCH   4
#define SEQ     2048
#define DIM     1024
#define NHEADS  16
#define DH      64
#define M_TOT   (BATCH * SEQ)   // 8192

__device__ float g_xt[M_TOT * DIM];
__device__ float g_wq[DIM * DIM];
__device__ float g_wk[DIM * DIM];
__device__ float g_wv[DIM * DIM];
__device__ float g_wo[DIM * DIM];
__device__ float g_q[M_TOT * DIM];
__device__ float g_k[M_TOT * DIM];
__device__ float g_v[M_TOT * DIM];     // V^T: [(b*1024 + h*64 + d) * SEQ + s]
__device__ float g_ctx[M_TOT * DIM];

// ---- helpers --------------------------------------------------------------
__device__ __forceinline__ uint32_t f2tf(float f) {
    uint32_t r;
    asm("cvt.rna.tf32.f32 %0, %1;" : "=r"(r) : "f"(f));
    return r;
}
__device__ __forceinline__ float ex2(float x) {
    float r;
    asm("ex2.approx.ftz.f32 %0, %1;" : "=f"(r) : "f"(x));
    return r;
}
__device__ __forceinline__ void mma8(float* c, const uint32_t* a, const uint32_t* b) {
    asm volatile(
        "mma.sync.aligned.m16n8k8.row.col.f32.tf32.tf32.f32 "
        "{%0,%1,%2,%3},{%4,%5,%6,%7},{%8,%9},{%0,%1,%2,%3};"
        : "+f"(c[0]), "+f"(c[1]), "+f"(c[2]), "+f"(c[3])
        : "r"(a[0]), "r"(a[1]), "r"(a[2]), "r"(a[3]), "r"(b[0]), "r"(b[1]));
}
__device__ __forceinline__ void ldsm4(uint32_t* r, const uint32_t* gptr) {
    uint32_t addr = (uint32_t)__cvta_generic_to_shared(gptr);
    asm volatile(
        "ldmatrix.sync.aligned.m8n8.x4.shared.b16 {%0,%1,%2,%3}, [%4];"
        : "=r"(r[0]), "=r"(r[1]), "=r"(r[2]), "=r"(r[3]) : "r"(addr));
}
__device__ __forceinline__ void cpasync16(void* dst, const void* src) {
    uint32_t d = (uint32_t)__cvta_generic_to_shared(dst);
    asm volatile("cp.async.cg.shared.global [%0], [%1], 16;" :: "r"(d), "l"(src));
}

extern __shared__ uint32_t dyn_smem[];

// ---------------------------------------------------------------------------
// Pre-truncation: dst = round_to_tf32(src). 4 float4 per thread, exact grid.
// ---------------------------------------------------------------------------
__global__ void trunc_kernel(const float* __restrict__ src, float* __restrict__ dst)
{
    int idx    = blockIdx.x * blockDim.x + threadIdx.x;
    int stride = gridDim.x * blockDim.x;
    #pragma unroll
    for (int u = 0; u < 4; u++) {
        int i = idx + u * stride;
        float4 v = ((const float4*)src)[i];
        ((uint4*)dst)[i] = make_uint4(f2tf(v.x), f2tf(v.y), f2tf(v.z), f2tf(v.w));
    }
}

// ---------------------------------------------------------------------------
// GEMM body: C[row0:+128, col0:+128] = alpha * A @ B (+bias), K = DIM.
// cp.async 2-stage. MODE: 0 = plain store, 1 = trunc store, 2 = trunc + V^T.
// ---------------------------------------------------------------------------
#define GBK   32
#define KT    (DIM / GBK)     // 32
#define A_ST  36
#define B_ST  132
#define A_TILE (128 * A_ST)
#define B_TILE (GBK * B_ST)
#define GEMM_SMEM ((2 * A_TILE + 2 * B_TILE) * 4)   // 70656 B

template <int MODE>
__device__ __forceinline__ void gemm_body(
    const float* __restrict__ A, const float* __restrict__ B, float* __restrict__ C,
    int row0, int col0, float alpha, const float* __restrict__ bias)
{
    uint32_t* As = dyn_smem;
    uint32_t* Bs = dyn_smem + 2 * A_TILE;

    const int tid  = threadIdx.x;
    const int lane = tid & 31;
    const int wid  = tid >> 5;
    const int wm   = wid >> 1;
    const int wn   = wid & 1;
    const int gid  = lane >> 2;
    const int t4   = lane & 3;
    const int lt     = lane >> 3;
    const int a_row  = (lane & 7) + (lt & 1) * 8;
    const int a_colb = (lt >> 1) * 4;

    const int ar = tid >> 3, ac4 = (tid & 7) * 4;
    const int bk = tid >> 5, bn4 = (tid & 31) * 4;

    float acc[2][8][4];
    #pragma unroll
    for (int mi = 0; mi < 2; mi++)
        #pragma unroll
        for (int j = 0; j < 8; j++)
            #pragma unroll
            for (int q = 0; q < 4; q++) acc[mi][j][q] = 0.0f;

    auto issue = [&](int kt_i, int buf) {
        int kt = kt_i * GBK;
        #pragma unroll
        for (int p = 0; p < 4; p++) {
            int r = ar + p * 32;
            cpasync16(&As[buf * A_TILE + r * A_ST + ac4],
                      &A[(size_t)(row0 + r) * DIM + kt + ac4]);
        }
        #pragma unroll
        for (int p = 0; p < 4; p++) {
            int k = bk + p * 8;
            cpasync16(&Bs[buf * B_TILE + k * B_ST + bn4],
                      &B[(size_t)(kt + k) * DIM + col0 + bn4]);
        }
        asm volatile("cp.async.commit_group;" ::);
    };

    issue(0, 0);
    for (int kt_i = 0; kt_i < KT; kt_i++) {
        if (kt_i + 1 < KT) {
            issue(kt_i + 1, (kt_i + 1) & 1);
            asm volatile("cp.async.wait_group 1;" ::);
        } else {
            asm volatile("cp.async.wait_group 0;" ::);
        }
        __syncthreads();

        const uint32_t* Asb = &As[(kt_i & 1) * A_TILE];
        const uint32_t* Bsb = &Bs[(kt_i & 1) * B_TILE];
        #pragma unroll
        for (int s = 0; s < 4; s++) {
            uint32_t af[2][4];
            #pragma unroll
            for (int mi = 0; mi < 2; mi++)
                ldsm4(af[mi], &Asb[(wm * 32 + mi * 16 + a_row) * A_ST + s * 8 + a_colb]);

            uint32_t bf[8][2];
            #pragma unroll
            for (int j = 0; j < 8; j++) {
                bf[j][0] = Bsb[(s * 8 + t4) * B_ST + wn * 64 + j * 8 + gid];
                bf[j][1] = Bsb[(s * 8 + 4 + t4) * B_ST + wn * 64 + j * 8 + gid];
            }
            #pragma unroll
            for (int mi = 0; mi < 2; mi++)
                #pragma unroll
                for (int j = 0; j < 8; j++)
                    mma8(acc[mi][j], af[mi], bf[j]);
        }
        __syncthreads();
    }

    // Epilogue
    #pragma unroll
    for (int mi = 0; mi < 2; mi++) {
        int r0 = row0 + wm * 32 + mi * 16 + gid;
        #pragma unroll
        for (int j = 0; j < 8; j++) {
            int c = col0 + wn * 64 + j * 8 + 2 * t4;
            float b0 = 0.0f, b1 = 0.0f;
            if (bias) { b0 = bias[c]; b1 = bias[c + 1]; }
            float o00 = acc[mi][j][0] * alpha + b0;
            float o01 = acc[mi][j][1] * alpha + b1;
            float o10 = acc[mi][j][2] * alpha + b0;
            float o11 = acc[mi][j][3] * alpha + b1;
            if (MODE == 2) {
                // V^T: addr = (b*1024 + c) * SEQ + s, with r = b*SEQ + s
                int b_0 = r0 >> 11, s_0 = r0 & 2047;
                int r1 = r0 + 8;
                int b_1 = r1 >> 11, s_1 = r1 & 2047;
                C[(size_t)(b_0 * 1024 + c)     * SEQ + s_0] = __uint_as_float(f2tf(o00));
                C[(size_t)(b_0 * 1024 + c + 1) * SEQ + s_0] = __uint_as_float(f2tf(o01));
                C[(size_t)(b_1 * 1024 + c)     * SEQ + s_1] = __uint_as_float(f2tf(o10));
                C[(size_t)(b_1 * 1024 + c + 1) * SEQ + s_1] = __uint_as_float(f2tf(o11));
            } else if (MODE == 1) {
                float2 v0 = make_float2(__uint_as_float(f2tf(o00)), __uint_as_float(f2tf(o01)));
                float2 v1 = make_float2(__uint_as_float(f2tf(o10)), __uint_as_float(f2tf(o11)));
                *(float2*)&C[(size_t)r0 * DIM + c]       = v0;
                *(float2*)&C[(size_t)(r0 + 8) * DIM + c] = v1;
            } else {
                *(float2*)&C[(size_t)r0 * DIM + c]       = make_float2(o00, o01);
                *(float2*)&C[(size_t)(r0 + 8) * DIM + c] = make_float2(o10, o11);
            }
        }
    }
}

#define Q_ALPHA 0.18033688011112042f   // 0.125 * log2(e)

__global__ __launch_bounds__(256, 2)
void qkv_gemm()
{
    int widx = blockIdx.x >> 3;
    int col0 = (blockIdx.x & 7) * 128;
    int row0 = blockIdx.y * 128;
    if (widx == 0)      gemm_body<1>(g_xt, g_wq, g_q, row0, col0, Q_ALPHA, nullptr);
    else if (widx == 1) gemm_body<1>(g_xt, g_wk, g_k, row0, col0, 1.0f, nullptr);
    else                gemm_body<2>(g_xt, g_wv, g_v, row0, col0, 1.0f, nullptr);
}

__global__ __launch_bounds__(256, 2)
void out_gemm(float* __restrict__ outp, const float* __restrict__ bias)
{
    gemm_body<0>(g_ctx, g_wo, outp, blockIdx.y * 128, blockIdx.x * 128, 1.0f, bias);
}

// ---------------------------------------------------------------------------
// Flash attention, tf32, cp.async double-buffered K/V^T, P in registers.
// 128 thr = 4 warps x 16 q-rows. BQ=64, BKV=64.
// ---------------------------------------------------------------------------
#define AQ   64
#define AKV  64
#define AST  (DH + 4)                 // 68
#define TILE_U32 (AKV * AST)          // 4352
#define ATTN_SMEM_BYTES (4 * TILE_U32 * 4)   // 69632

__global__ __launch_bounds__(128, 3)
void attn_tf32(float* __restrict__ O)
{
    const float* Qg = g_q;
    const float* Kg = g_k;
    const float* Vg = g_v;   // V^T

    uint32_t* Ks = dyn_smem;                 // [2][64][68]
    uint32_t* Vt = dyn_smem + 2 * TILE_U32;  // [2][64][68]

    const int tid  = threadIdx.x;
    const int lane = tid & 31;
    const int w    = tid >> 5;
    const int gid  = lane >> 2;
    const int t4   = lane & 3;
    const int q0   = blockIdx.x * AQ;
    const int bh   = blockIdx.y;
    const size_t base    = (size_t)(bh >> 4) * SEQ * DIM + (size_t)(bh & 15) * DH;
    const size_t base_vt = (size_t)((bh >> 4) * 1024 + (bh & 15) * DH) * SEQ;

    const int lt     = lane >> 3;
    const int a_row  = (lane & 7) + (lt & 1) * 8;
    const int a_colb = (lt >> 1) * 4;
    const int b_rowb = (lt >> 1) * 8;
    const int b_row  = (lane & 7);
    const int b_colb = (lt & 1) * 4;

    // ---- Stage Q into Ks[0], extract A-fragments ----
    #pragma unroll
    for (int p = 0; p < 8; p++) {
        int r  = (tid >> 4) + p * 8;
        int c4 = (tid & 15) * 4;
        *(uint4*)&Ks[r * AST + c4] =
            *(const uint4*)&Qg[base + (size_t)(q0 + r) * DIM + c4];
    }
    __syncthreads();
    uint32_t qa[8][4];
    #pragma unroll
    for (int s = 0; s < 8; s++)
        ldsm4(qa[s], &Ks[(w * 16 + a_row) * AST + s * 8 + a_colb]);
    __syncthreads();

    // loader coords: 4 threads per row, 4 chunks/row/thread over 2 row passes
    const int lrow = tid >> 2;          // 0..31
    const int lq4  = (tid & 3) * 4;     // 0,4,8,12 (float offset within 16-chunk grp)

    auto issue = [&](int kt_i, int buf) {
        int kt = kt_i * AKV;
        #pragma unroll
        for (int pass = 0; pass < 2; pass++) {
            int r = lrow + pass * 32;
            #pragma unroll
            for (int p = 0; p < 4; p++) {
                int col = lq4 + p * 16;
                cpasync16(&Ks[buf * TILE_U32 + r * AST + col],
                          &Kg[base + (size_t)(kt + r) * DIM + col]);
                cpasync16(&Vt[buf * TILE_U32 + r * AST + col],
                          &Vg[base_vt + (size_t)r * SEQ + kt + col]);
            }
        }
        asm volatile("cp.async.commit_group;" ::);
    };

    float m0 = -1e30f, m1 = -1e30f, l0 = 0.0f, l1 = 0.0f;
    float oc[8][4];
    #pragma unroll
    for (int j = 0; j < 8; j++)
        #pragma unroll
        for (int q = 0; q < 4; q++) oc[j][q] = 0.0f;

    issue(0, 0);
    const int NT = SEQ / AKV;   // 32
    for (int i = 0; i < NT; i++) {
        if (i + 1 < NT) {
            issue(i + 1, (i + 1) & 1);
            asm volatile("cp.async.wait_group 1;" ::);
        } else {
            asm volatile("cp.async.wait_group 0;" ::);
        }
        __syncthreads();

        const uint32_t* Ksb = &Ks[(i & 1) * TILE_U32];
        const uint32_t* Vtb = &Vt[(i & 1) * TILE_U32];

        // ---- S = Q @ K^T ----
        float sc[8][4];
        #pragma unroll
        for (int j = 0; j < 8; j++)
            #pragma unroll
            for (int q = 0; q < 4; q++) sc[j][q] = 0.0f;

        #pragma unroll
        for (int s = 0; s < 8; s++) {
            uint32_t kb[8][2];
            #pragma unroll
            for (int jp = 0; jp < 4; jp++) {
                uint32_t r4[4];
                ldsm4(r4, &Ksb[(jp * 16 + b_rowb + b_row) * AST + s * 8 + b_colb]);
                kb[jp * 2][0]     = r4[0];
                kb[jp * 2][1]     = r4[1];
                kb[jp * 2 + 1][0] = r4[2];
                kb[jp * 2 + 1][1] = r4[3];
            }
            #pragma unroll
            for (int j = 0; j < 8; j++)
                mma8(sc[j], qa[s], kb[j]);
        }

        // ---- online softmax (log2 domain); sc becomes tf32-rounded P ----
        float mx0 = -1e30f, mx1 = -1e30f;
        #pragma unroll
        for (int j = 0; j < 8; j++) {
            mx0 = fmaxf(mx0, fmaxf(sc[j][0], sc[j][1]));
            mx1 = fmaxf(mx1, fmaxf(sc[j][2], sc[j][3]));
        }
        mx0 = fmaxf(mx0, __shfl_xor_sync(0xffffffffu, mx0, 1));
        mx0 = fmaxf(mx0, __shfl_xor_sync(0xffffffffu, mx0, 2));
        mx1 = fmaxf(mx1, __shfl_xor_sync(0xffffffffu, mx1, 1));
        mx1 = fmaxf(mx1, __shfl_xor_sync(0xffffffffu, mx1, 2));
        float mn0 = fmaxf(m0, mx0), mn1 = fmaxf(m1, mx1);
        float cr0 = ex2(m0 - mn0), cr1 = ex2(m1 - mn1);
        m0 = mn0; m1 = mn1;

        float s0 = 0.0f, s1 = 0.0f;
        #pragma unroll
        for (int j = 0; j < 8; j++) {
            float p0 = __uint_as_float(f2tf(ex2(sc[j][0] - mn0)));
            float p1 = __uint_as_float(f2tf(ex2(sc[j][1] - mn0)));
            float p2 = __uint_as_float(f2tf(ex2(sc[j][2] - mn1)));
            float p3 = __uint_as_float(f2tf(ex2(sc[j][3] - mn1)));
            s0 += p0 + p1; s1 += p2 + p3;
            sc[j][0] = p0; sc[j][1] = p1; sc[j][2] = p2; sc[j][3] = p3;
        }
        s0 += __shfl_xor_sync(0xffffffffu, s0, 1);
        s0 += __shfl_xor_sync(0xffffffffu, s0, 2);
        s1 += __shfl_xor_sync(0xffffffffu, s1, 1);
        s1 += __shfl_xor_sync(0xffffffffu, s1, 2);
        l0 = l0 * cr0 + s0;
        l1 = l1 * cr1 + s1;
        #pragma unroll
        for (int j = 0; j < 8; j++) {
            oc[j][0] *= cr0; oc[j][1] *= cr0;
            oc[j][2] *= cr1; oc[j][3] *= cr1;
        }

        // ---- O += P @ V : build P A-fragments via quad shuffles ----
        const int src0 = (lane & ~3) | (t4 >> 1);
        const int src2 = src0 + 2;
        const bool odd = (t4 & 1);
        #pragma unroll
        for (int s = 0; s < 8; s++) {
            uint32_t c0 = __float_as_uint(sc[s][0]);
            uint32_t c1 = __float_as_uint(sc[s][1]);
            uint32_t c2 = __float_as_uint(sc[s][2]);
            uint32_t c3 = __float_as_uint(sc[s][3]);
            uint32_t pa[4];
            uint32_t e0 = __shfl_sync(0xffffffffu, c0, src0);
            uint32_t e1 = __shfl_sync(0xffffffffu, c1, src0);
            uint32_t f0 = __shfl_sync(0xffffffffu, c2, src0);
            uint32_t f1 = __shfl_sync(0xffffffffu, c3, src0);
            uint32_t g0 = __shfl_sync(0xffffffffu, c0, src2);
            uint32_t g1 = __shfl_sync(0xffffffffu, c1, src2);
            uint32_t h0 = __shfl_sync(0xffffffffu, c2, src2);
            uint32_t h1 = __shfl_sync(0xffffffffu, c3, src2);
            pa[0] = odd ? e1 : e0;
            pa[1] = odd ? f1 : f0;
            pa[2] = odd ? g1 : g0;
            pa[3] = odd ? h1 : h0;
            #pragma unroll
            for (int jp = 0; jp < 4; jp++) {
                uint32_t r4[4];
                ldsm4(r4, &Vtb[(jp * 16 + b_rowb + b_row) * AST + s * 8 + b_colb]);
                mma8(oc[jp * 2],     pa, &r4[0]);
                mma8(oc[jp * 2 + 1], pa, &r4[2]);
            }
        }
        __syncthreads();
    }

    // Epilogue: normalize + truncate (ctx feeds tf32 GEMM)
    float inv0 = 1.0f / l0, inv1 = 1.0f / l1;
    int r0 = q0 + w * 16 + gid;
    #pragma unroll
    for (int j = 0; j < 8; j++) {
        int c = j * 8 + 2 * t4;
        uint2 v0 = { f2tf(oc[j][0] * inv0), f2tf(oc[j][1] * inv0) };
        uint2 v1 = { f2tf(oc[j][2] * inv1), f2tf(oc[j][3] * inv1) };
        *(uint2*)&O[base + (size_t)r0 * DIM + c]       = v0;
        *(uint2*)&O[base + (size_t)(r0 + 8) * DIM + c] = v1;
    }
}

// ---------------------------------------------------------------------------
// Launch
// ---------------------------------------------------------------------------
extern "C" void kernel_launch(void* const* d_in, const int* in_sizes, int n_in,
                              void* d_out, int out_size)
{
    const float* x  = (const float*)d_in[0];
    const float* Wq = (const float*)d_in[1];
    const float* Wk = (const float*)d_in[2];
    const float* Wv = (const float*)d_in[3];
    const float* Wo = (const float*)d_in[4];
    const float* bo = (const float*)d_in[5];
    float* out = (float*)d_out;

    float *xt, *wq, *wk, *wv, *wo, *ctx;
    cudaGetSymbolAddress((void**)&xt,  g_xt);
    cudaGetSymbolAddress((void**)&wq,  g_wq);
    cudaGetSymbolAddress((void**)&wk,  g_wk);
    cudaGetSymbolAddress((void**)&wv,  g_wv);
    cudaGetSymbolAddress((void**)&wo,  g_wo);
    cudaGetSymbolAddress((void**)&ctx, g_ctx);

    cudaFuncSetAttribute(qkv_gemm, cudaFuncAttributeMaxDynamicSharedMemorySize, GEMM_SMEM);
    cudaFuncSetAttribute(out_gemm, cudaFuncAttributeMaxDynamicSharedMemorySize, GEMM_SMEM);
    cudaFuncSetAttribute(attn_tf32, cudaFuncAttributeMaxDynamicSharedMemorySize, ATTN_SMEM_BYTES);

    // Pre-truncate inputs (x: 2M float4 / (256 thr * 4) = 2048 blocks)
    trunc_kernel<<<2048, 256>>>(x, xt);
    trunc_kernel<<<256, 256>>>(Wq, wq);
    trunc_kernel<<<256, 256>>>(Wk, wk);
    trunc_kernel<<<256, 256>>>(Wv, wv);
    trunc_kernel<<<256, 256>>>(Wo, wo);

    qkv_gemm<<<dim3(24, M_TOT / 128), 256, GEMM_SMEM>>>();
    attn_tf32<<<dim3(SEQ / AQ, BATCH * NHEADS), 128, ATTN_SMEM_BYTES>>>(ctx);
    out_gemm<<<dim3(DIM / 128, M_TOT / 128), 256, GEMM_SMEM>>>(out, bo);
}

// round 6
// speedup vs baseline: 4.1171x; 1.0501x over previous
#include <cuda_runtime.h>
#include <stdint.h>

// ---------------------------------------------------------------------------
// MultiHeadSelfAttention, tf32 mma.sync.
// R6: attention at BQ=128 / 256 threads (16 warps/SM), fused weight trunc.
// ---------------------------------------------------------------------------

#define BATCH   4
#define SEQ     2048
#define DIM     1024
#define NHEADS  16
#define DH      64
#define M_TOT   (BATCH * SEQ)   // 8192

__device__ float g_xt[M_TOT * DIM];
__device__ float g_wq[DIM * DIM];
__device__ float g_wk[DIM * DIM];
__device__ float g_wv[DIM * DIM];
__device__ float g_wo[DIM * DIM];
__device__ float g_q[M_TOT * DIM];
__device__ float g_k[M_TOT * DIM];
__device__ float g_v[M_TOT * DIM];     // V^T: [(b*1024 + h*64 + d) * SEQ + s]
__device__ float g_ctx[M_TOT * DIM];

// ---- helpers --------------------------------------------------------------
__device__ __forceinline__ uint32_t f2tf(float f) {
    uint32_t r;
    asm("cvt.rna.tf32.f32 %0, %1;" : "=r"(r) : "f"(f));
    return r;
}
__device__ __forceinline__ float ex2(float x) {
    float r;
    asm("ex2.approx.ftz.f32 %0, %1;" : "=f"(r) : "f"(x));
    return r;
}
__device__ __forceinline__ void mma8(float* c, const uint32_t* a, const uint32_t* b) {
    asm volatile(
        "mma.sync.aligned.m16n8k8.row.col.f32.tf32.tf32.f32 "
        "{%0,%1,%2,%3},{%4,%5,%6,%7},{%8,%9},{%0,%1,%2,%3};"
        : "+f"(c[0]), "+f"(c[1]), "+f"(c[2]), "+f"(c[3])
        : "r"(a[0]), "r"(a[1]), "r"(a[2]), "r"(a[3]), "r"(b[0]), "r"(b[1]));
}
__device__ __forceinline__ void ldsm4(uint32_t* r, const uint32_t* gptr) {
    uint32_t addr = (uint32_t)__cvta_generic_to_shared(gptr);
    asm volatile(
        "ldmatrix.sync.aligned.m8n8.x4.shared.b16 {%0,%1,%2,%3}, [%4];"
        : "=r"(r[0]), "=r"(r[1]), "=r"(r[2]), "=r"(r[3]) : "r"(addr));
}
__device__ __forceinline__ void cpasync16(void* dst, const void* src) {
    uint32_t d = (uint32_t)__cvta_generic_to_shared(dst);
    asm volatile("cp.async.cg.shared.global [%0], [%1], 16;" :: "r"(d), "l"(src));
}

extern __shared__ uint32_t dyn_smem[];

// ---------------------------------------------------------------------------
// Pre-truncation kernels.
// ---------------------------------------------------------------------------
__global__ void trunc_x_kernel(const float* __restrict__ src, float* __restrict__ dst)
{
    int idx    = blockIdx.x * blockDim.x + threadIdx.x;
    int stride = gridDim.x * blockDim.x;
    #pragma unroll
    for (int u = 0; u < 4; u++) {
        int i = idx + u * stride;
        float4 v = ((const float4*)src)[i];
        ((uint4*)dst)[i] = make_uint4(f2tf(v.x), f2tf(v.y), f2tf(v.z), f2tf(v.w));
    }
}

// One launch truncates all 4 weights; blockIdx.y selects which.
__global__ void trunc_w_kernel(const float* __restrict__ Wq, const float* __restrict__ Wk,
                               const float* __restrict__ Wv, const float* __restrict__ Wo)
{
    const float* src;
    float* dst;
    switch (blockIdx.y) {
        case 0:  src = Wq; dst = g_wq; break;
        case 1:  src = Wk; dst = g_wk; break;
        case 2:  src = Wv; dst = g_wv; break;
        default: src = Wo; dst = g_wo; break;
    }
    int idx    = blockIdx.x * blockDim.x + threadIdx.x;
    int stride = gridDim.x * blockDim.x;
    #pragma unroll
    for (int u = 0; u < 4; u++) {
        int i = idx + u * stride;
        float4 v = ((const float4*)src)[i];
        ((uint4*)dst)[i] = make_uint4(f2tf(v.x), f2tf(v.y), f2tf(v.z), f2tf(v.w));
    }
}

// ---------------------------------------------------------------------------
// GEMM body: C[row0:+128, col0:+128] = alpha * A @ B (+bias), K = DIM.
// cp.async 2-stage. MODE: 0 = plain store, 1 = trunc store, 2 = trunc + V^T.
// ---------------------------------------------------------------------------
#define GBK   32
#define KT    (DIM / GBK)     // 32
#define A_ST  36
#define B_ST  132
#define A_TILE (128 * A_ST)
#define B_TILE (GBK * B_ST)
#define GEMM_SMEM ((2 * A_TILE + 2 * B_TILE) * 4)   // 70656 B

template <int MODE>
__device__ __forceinline__ void gemm_body(
    const float* __restrict__ A, const float* __restrict__ B, float* __restrict__ C,
    int row0, int col0, float alpha, const float* __restrict__ bias)
{
    uint32_t* As = dyn_smem;
    uint32_t* Bs = dyn_smem + 2 * A_TILE;

    const int tid  = threadIdx.x;
    const int lane = tid & 31;
    const int wid  = tid >> 5;
    const int wm   = wid >> 1;
    const int wn   = wid & 1;
    const int gid  = lane >> 2;
    const int t4   = lane & 3;
    const int lt     = lane >> 3;
    const int a_row  = (lane & 7) + (lt & 1) * 8;
    const int a_colb = (lt >> 1) * 4;

    const int ar = tid >> 3, ac4 = (tid & 7) * 4;
    const int bk = tid >> 5, bn4 = (tid & 31) * 4;

    float acc[2][8][4];
    #pragma unroll
    for (int mi = 0; mi < 2; mi++)
        #pragma unroll
        for (int j = 0; j < 8; j++)
            #pragma unroll
            for (int q = 0; q < 4; q++) acc[mi][j][q] = 0.0f;

    auto issue = [&](int kt_i, int buf) {
        int kt = kt_i * GBK;
        #pragma unroll
        for (int p = 0; p < 4; p++) {
            int r = ar + p * 32;
            cpasync16(&As[buf * A_TILE + r * A_ST + ac4],
                      &A[(size_t)(row0 + r) * DIM + kt + ac4]);
        }
        #pragma unroll
        for (int p = 0; p < 4; p++) {
            int k = bk + p * 8;
            cpasync16(&Bs[buf * B_TILE + k * B_ST + bn4],
                      &B[(size_t)(kt + k) * DIM + col0 + bn4]);
        }
        asm volatile("cp.async.commit_group;" ::);
    };

    issue(0, 0);
    for (int kt_i = 0; kt_i < KT; kt_i++) {
        if (kt_i + 1 < KT) {
            issue(kt_i + 1, (kt_i + 1) & 1);
            asm volatile("cp.async.wait_group 1;" ::);
        } else {
            asm volatile("cp.async.wait_group 0;" ::);
        }
        __syncthreads();

        const uint32_t* Asb = &As[(kt_i & 1) * A_TILE];
        const uint32_t* Bsb = &Bs[(kt_i & 1) * B_TILE];
        #pragma unroll
        for (int s = 0; s < 4; s++) {
            uint32_t af[2][4];
            #pragma unroll
            for (int mi = 0; mi < 2; mi++)
                ldsm4(af[mi], &Asb[(wm * 32 + mi * 16 + a_row) * A_ST + s * 8 + a_colb]);

            uint32_t bf[8][2];
            #pragma unroll
            for (int j = 0; j < 8; j++) {
                bf[j][0] = Bsb[(s * 8 + t4) * B_ST + wn * 64 + j * 8 + gid];
                bf[j][1] = Bsb[(s * 8 + 4 + t4) * B_ST + wn * 64 + j * 8 + gid];
            }
            #pragma unroll
            for (int mi = 0; mi < 2; mi++)
                #pragma unroll
                for (int j = 0; j < 8; j++)
                    mma8(acc[mi][j], af[mi], bf[j]);
        }
        __syncthreads();
    }

    #pragma unroll
    for (int mi = 0; mi < 2; mi++) {
        int r0 = row0 + wm * 32 + mi * 16 + gid;
        #pragma unroll
        for (int j = 0; j < 8; j++) {
            int c = col0 + wn * 64 + j * 8 + 2 * t4;
            float b0 = 0.0f, b1 = 0.0f;
            if (bias) { b0 = bias[c]; b1 = bias[c + 1]; }
            float o00 = acc[mi][j][0] * alpha + b0;
            float o01 = acc[mi][j][1] * alpha + b1;
            float o10 = acc[mi][j][2] * alpha + b0;
            float o11 = acc[mi][j][3] * alpha + b1;
            if (MODE == 2) {
                int b_0 = r0 >> 11, s_0 = r0 & 2047;
                int r1 = r0 + 8;
                int b_1 = r1 >> 11, s_1 = r1 & 2047;
                C[(size_t)(b_0 * 1024 + c)     * SEQ + s_0] = __uint_as_float(f2tf(o00));
                C[(size_t)(b_0 * 1024 + c + 1) * SEQ + s_0] = __uint_as_float(f2tf(o01));
                C[(size_t)(b_1 * 1024 + c)     * SEQ + s_1] = __uint_as_float(f2tf(o10));
                C[(size_t)(b_1 * 1024 + c + 1) * SEQ + s_1] = __uint_as_float(f2tf(o11));
            } else if (MODE == 1) {
                float2 v0 = make_float2(__uint_as_float(f2tf(o00)), __uint_as_float(f2tf(o01)));
                float2 v1 = make_float2(__uint_as_float(f2tf(o10)), __uint_as_float(f2tf(o11)));
                *(float2*)&C[(size_t)r0 * DIM + c]       = v0;
                *(float2*)&C[(size_t)(r0 + 8) * DIM + c] = v1;
            } else {
                *(float2*)&C[(size_t)r0 * DIM + c]       = make_float2(o00, o01);
                *(float2*)&C[(size_t)(r0 + 8) * DIM + c] = make_float2(o10, o11);
            }
        }
    }
}

#define Q_ALPHA 0.18033688011112042f   // 0.125 * log2(e)

__global__ __launch_bounds__(256, 2)
void qkv_gemm()
{
    int widx = blockIdx.x >> 3;
    int col0 = (blockIdx.x & 7) * 128;
    int row0 = blockIdx.y * 128;
    if (widx == 0)      gemm_body<1>(g_xt, g_wq, g_q, row0, col0, Q_ALPHA, nullptr);
    else if (widx == 1) gemm_body<1>(g_xt, g_wk, g_k, row0, col0, 1.0f, nullptr);
    else                gemm_body<2>(g_xt, g_wv, g_v, row0, col0, 1.0f, nullptr);
}

__global__ __launch_bounds__(256, 2)
void out_gemm(float* __restrict__ outp, const float* __restrict__ bias)
{
    gemm_body<0>(g_ctx, g_wo, outp, blockIdx.y * 128, blockIdx.x * 128, 1.0f, bias);
}

// ---------------------------------------------------------------------------
// Flash attention, tf32. BQ=128 (8 warps x 16 q-rows), BKV=64,
// cp.async double-buffered K/V^T, P in registers. 2 CTAs/SM -> 16 warps.
// ---------------------------------------------------------------------------
#define AQ   128
#define AKV  64
#define AST  (DH + 4)                 // 68
#define TILE_U32 (AKV * AST)          // 4352
#define ATTN_SMEM_BYTES (4 * TILE_U32 * 4)   // 69632

__global__ __launch_bounds__(256, 2)
void attn_tf32(float* __restrict__ O)
{
    const float* Qg = g_q;
    const float* Kg = g_k;
    const float* Vg = g_v;   // V^T

    uint32_t* Ks = dyn_smem;                 // [2][64][68]
    uint32_t* Vt = dyn_smem + 2 * TILE_U32;  // [2][64][68]

    const int tid  = threadIdx.x;
    const int lane = tid & 31;
    const int w    = tid >> 5;               // 0..7
    const int gid  = lane >> 2;
    const int t4   = lane & 3;
    const int q0   = blockIdx.x * AQ;
    const int bh   = blockIdx.y;
    const size_t base    = (size_t)(bh >> 4) * SEQ * DIM + (size_t)(bh & 15) * DH;
    const size_t base_vt = (size_t)((bh >> 4) * 1024 + (bh & 15) * DH) * SEQ;

    const int lt     = lane >> 3;
    const int a_row  = (lane & 7) + (lt & 1) * 8;
    const int a_colb = (lt >> 1) * 4;
    const int b_rowb = (lt >> 1) * 8;
    const int b_row  = (lane & 7);
    const int b_colb = (lt & 1) * 4;

    // ---- Stage Q (128 x 64) into the two K buffers (exactly 8704 u32) ----
    #pragma unroll
    for (int p = 0; p < 8; p++) {
        int r  = (tid >> 4) + p * 16;        // 0..127
        int c4 = (tid & 15) * 4;
        *(uint4*)&Ks[r * AST + c4] =
            *(const uint4*)&Qg[base + (size_t)(q0 + r) * DIM + c4];
    }
    __syncthreads();
    uint32_t qa[8][4];
    #pragma unroll
    for (int s = 0; s < 8; s++)
        ldsm4(qa[s], &Ks[(w * 16 + a_row) * AST + s * 8 + a_colb]);
    __syncthreads();

    // loader coords: 4 threads per row over 64 rows
    const int lrow = tid >> 2;          // 0..63
    const int lq4  = (tid & 3) * 4;     // 0,4,8,12

    auto issue = [&](int kt_i, int buf) {
        int kt = kt_i * AKV;
        #pragma unroll
        for (int p = 0; p < 4; p++) {
            int col = lq4 + p * 16;
            cpasync16(&Ks[buf * TILE_U32 + lrow * AST + col],
                      &Kg[base + (size_t)(kt + lrow) * DIM + col]);
            cpasync16(&Vt[buf * TILE_U32 + lrow * AST + col],
                      &Vg[base_vt + (size_t)lrow * SEQ + kt + col]);
        }
        asm volatile("cp.async.commit_group;" ::);
    };

    float m0 = -1e30f, m1 = -1e30f, l0 = 0.0f, l1 = 0.0f;
    float oc[8][4];
    #pragma unroll
    for (int j = 0; j < 8; j++)
        #pragma unroll
        for (int q = 0; q < 4; q++) oc[j][q] = 0.0f;

    issue(0, 0);
    const int NT = SEQ / AKV;   // 32
    for (int i = 0; i < NT; i++) {
        if (i + 1 < NT) {
            issue(i + 1, (i + 1) & 1);
            asm volatile("cp.async.wait_group 1;" ::);
        } else {
            asm volatile("cp.async.wait_group 0;" ::);
        }
        __syncthreads();

        const uint32_t* Ksb = &Ks[(i & 1) * TILE_U32];
        const uint32_t* Vtb = &Vt[(i & 1) * TILE_U32];

        // ---- S = Q @ K^T ----
        float sc[8][4];
        #pragma unroll
        for (int j = 0; j < 8; j++)
            #pragma unroll
            for (int q = 0; q < 4; q++) sc[j][q] = 0.0f;

        #pragma unroll
        for (int s = 0; s < 8; s++) {
            uint32_t kb[8][2];
            #pragma unroll
            for (int jp = 0; jp < 4; jp++) {
                uint32_t r4[4];
                ldsm4(r4, &Ksb[(jp * 16 + b_rowb + b_row) * AST + s * 8 + b_colb]);
                kb[jp * 2][0]     = r4[0];
                kb[jp * 2][1]     = r4[1];
                kb[jp * 2 + 1][0] = r4[2];
                kb[jp * 2 + 1][1] = r4[3];
            }
            #pragma unroll
            for (int j = 0; j < 8; j++)
                mma8(sc[j], qa[s], kb[j]);
        }

        // ---- online softmax (log2 domain); sc becomes tf32-rounded P ----
        float mx0 = -1e30f, mx1 = -1e30f;
        #pragma unroll
        for (int j = 0; j < 8; j++) {
            mx0 = fmaxf(mx0, fmaxf(sc[j][0], sc[j][1]));
            mx1 = fmaxf(mx1, fmaxf(sc[j][2], sc[j][3]));
        }
        mx0 = fmaxf(mx0, __shfl_xor_sync(0xffffffffu, mx0, 1));
        mx0 = fmaxf(mx0, __shfl_xor_sync(0xffffffffu, mx0, 2));
        mx1 = fmaxf(mx1, __shfl_xor_sync(0xffffffffu, mx1, 1));
        mx1 = fmaxf(mx1, __shfl_xor_sync(0xffffffffu, mx1, 2));
        float mn0 = fmaxf(m0, mx0), mn1 = fmaxf(m1, mx1);
        float cr0 = ex2(m0 - mn0), cr1 = ex2(m1 - mn1);
        m0 = mn0; m1 = mn1;

        float s0 = 0.0f, s1 = 0.0f;
        #pragma unroll
        for (int j = 0; j < 8; j++) {
            float p0 = __uint_as_float(f2tf(ex2(sc[j][0] - mn0)));
            float p1 = __uint_as_float(f2tf(ex2(sc[j][1] - mn0)));
            float p2 = __uint_as_float(f2tf(ex2(sc[j][2] - mn1)));
            float p3 = __uint_as_float(f2tf(ex2(sc[j][3] - mn1)));
            s0 += p0 + p1; s1 += p2 + p3;
            sc[j][0] = p0; sc[j][1] = p1; sc[j][2] = p2; sc[j][3] = p3;
        }
        s0 += __shfl_xor_sync(0xffffffffu, s0, 1);
        s0 += __shfl_xor_sync(0xffffffffu, s0, 2);
        s1 += __shfl_xor_sync(0xffffffffu, s1, 1);
        s1 += __shfl_xor_sync(0xffffffffu, s1, 2);
        l0 = l0 * cr0 + s0;
        l1 = l1 * cr1 + s1;
        #pragma unroll
        for (int j = 0; j < 8; j++) {
            oc[j][0] *= cr0; oc[j][1] *= cr0;
            oc[j][2] *= cr1; oc[j][3] *= cr1;
        }

        // ---- O += P @ V : P A-fragments via quad shuffles ----
        const int src0 = (lane & ~3) | (t4 >> 1);
        const int src2 = src0 + 2;
        const bool odd = (t4 & 1);
        #pragma unroll
        for (int s = 0; s < 8; s++) {
            uint32_t c0 = __float_as_uint(sc[s][0]);
            uint32_t c1 = __float_as_uint(sc[s][1]);
            uint32_t c2 = __float_as_uint(sc[s][2]);
            uint32_t c3 = __float_as_uint(sc[s][3]);
            uint32_t pa[4];
            uint32_t e0 = __shfl_sync(0xffffffffu, c0, src0);
            uint32_t e1 = __shfl_sync(0xffffffffu, c1, src0);
            uint32_t f0 = __shfl_sync(0xffffffffu, c2, src0);
            uint32_t f1 = __shfl_sync(0xffffffffu, c3, src0);
            uint32_t g0 = __shfl_sync(0xffffffffu, c0, src2);
            uint32_t g1 = __shfl_sync(0xffffffffu, c1, src2);
            uint32_t h0 = __shfl_sync(0xffffffffu, c2, src2);
            uint32_t h1 = __shfl_sync(0xffffffffu, c3, src2);
            pa[0] = odd ? e1 : e0;
            pa[1] = odd ? f1 : f0;
            pa[2] = odd ? g1 : g0;
            pa[3] = odd ? h1 : h0;
            #pragma unroll
            for (int jp = 0; jp < 4; jp++) {
                uint32_t r4[4];
                ldsm4(r4, &Vtb[(jp * 16 + b_rowb + b_row) * AST + s * 8 + b_colb]);
                mma8(oc[jp * 2],     pa, &r4[0]);
                mma8(oc[jp * 2 + 1], pa, &r4[2]);
            }
        }
        __syncthreads();
    }

    // Epilogue: normalize + truncate (ctx feeds tf32 GEMM)
    float inv0 = 1.0f / l0, inv1 = 1.0f / l1;
    int r0 = q0 + w * 16 + gid;
    #pragma unroll
    for (int j = 0; j < 8; j++) {
        int c = j * 8 + 2 * t4;
        uint2 v0 = { f2tf(oc[j][0] * inv0), f2tf(oc[j][1] * inv0) };
        uint2 v1 = { f2tf(oc[j][2] * inv1), f2tf(oc[j][3] * inv1) };
        *(uint2*)&O[base + (size_t)r0 * DIM + c]       = v0;
        *(uint2*)&O[base + (size_t)(r0 + 8) * DIM + c] = v1;
    }
}

// ---------------------------------------------------------------------------
// Launch
// ---------------------------------------------------------------------------
extern "C" void kernel_launch(void* const* d_in, const int* in_sizes, int n_in,
                              void* d_out, int out_size)
{
    const float* x  = (const float*)d_in[0];
    const float* Wq = (const float*)d_in[1];
    const float* Wk = (const float*)d_in[2];
    const float* Wv = (const float*)d_in[3];
    const float* Wo = (const float*)d_in[4];
    const float* bo = (const float*)d_in[5];
    float* out = (float*)d_out;

    float *xt, *ctx;
    cudaGetSymbolAddress((void**)&xt,  g_xt);
    cudaGetSymbolAddress((void**)&ctx, g_ctx);

    cudaFuncSetAttribute(qkv_gemm, cudaFuncAttributeMaxDynamicSharedMemorySize, GEMM_SMEM);
    cudaFuncSetAttribute(out_gemm, cudaFuncAttributeMaxDynamicSharedMemorySize, GEMM_SMEM);
    cudaFuncSetAttribute(attn_tf32, cudaFuncAttributeMaxDynamicSharedMemorySize, ATTN_SMEM_BYTES);

    trunc_x_kernel<<<2048, 256>>>(x, xt);
    trunc_w_kernel<<<dim3(256, 4), 256>>>(Wq, Wk, Wv, Wo);

    qkv_gemm<<<dim3(24, M_TOT / 128), 256, GEMM_SMEM>>>();
    attn_tf32<<<dim3(SEQ / AQ, BATCH * NHEADS), 256, ATTN_SMEM_BYTES>>>(ctx);
    out_gemm<<<dim3(DIM / 128, M_TOT / 128), 256, GEMM_SMEM>>>(out, bo);
}